// round 17
// baseline (speedup 1.0000x reference)
#include <cuda_runtime.h>
#include <cstdint>

#define FULL_MASK 0xffffffffu
#define CHUNK 1024
#define WARM  512
#define TILE  512      // 16 elems/lane * 32 lanes
#define CPR   6
#define FDIM  80

// PCEN: out = (x / (FLOOR + ema)^a + d)^(1/r) - d^(1/r)
// ema[t] = (1-s)*ema[t-1] + s*x[t], ema[0] = x[0]
// n = ema + FLOOR tracked directly: n_t = c*n_{t-1} + (s*x_t + s*FLOOR).
// One warp per 1024-elem chunk; chunk j>0 warms on the preceding 512 elems
// (dropped carry ~c^512 ~ 9e-10). Last chunk realigned to [T-CHUNK, T):
// benign ~1e-9 double-write overlap.
// TWO-PASS 512-elem tiles: pass 1 = 4x LDG.128 + rolling lane aggregate
// (no arrays) + 5-shfl warpscan (hop c^16) -> kappa; pass 2 = re-load from
// L1 and run the exact sequential recurrence from kappa, storing outputs.
// Register-neutral chain amortization: no l[]/t[] arrays ever live.

__device__ __forceinline__ float f_sqrt(float x){ float y; asm("sqrt.approx.f32 %0, %1;" : "=f"(y) : "f"(x)); return y; }
__device__ __forceinline__ float f_lg2 (float x){ float y; asm("lg2.approx.f32 %0, %1;"  : "=f"(y) : "f"(x)); return y; }
__device__ __forceinline__ float f_ex2 (float x){ float y; asm("ex2.approx.f32 %0, %1;"  : "=f"(y) : "f"(x)); return y; }
__device__ __forceinline__ void st_cs(float* p, float4 v){
    asm volatile("st.global.cs.v4.f32 [%0], {%1,%2,%3,%4};" :: "l"(p), "f"(v.x), "f"(v.y), "f"(v.z), "f"(v.w) : "memory");
}

__global__ __launch_bounds__(128)
void pcen_kernel(const float* __restrict__ x,
                 const float* __restrict__ smooth,
                 const float* __restrict__ alpha,
                 const float* __restrict__ delta,
                 const float* __restrict__ root,
                 float* __restrict__ out,
                 int rows, int T)
{
    const int gw   = (int)((blockIdx.x * blockDim.x + threadIdx.x) >> 5);
    const int lane = threadIdx.x & 31;
    if (gw >= rows * CPR) return;
    const int row = gw / CPR;
    const int ck  = gw - row * CPR;
    const int f   = row % FDIM;

    // per-feature params (warp-uniform)
    const float s = fminf(fmaxf(smooth[f], 0.0f), 1.0f);
    const float c = 1.0f - s;
    const float a = fminf(alpha[f], 1.0f);
    const float r = fmaxf(root[f], 1.0f);
    const float d = delta[f];
    const float inv_r = 1.0f / r;
    const bool  r2 = (r == 2.0f);
    const float dr = r2 ? f_sqrt(d) : __powf(d, inv_r);
    const float se = s * 1e-6f;

    const float c2  = c * c;
    const float c4  = c2 * c2;
    const float c8  = c4 * c4;
    const float c16 = c8 * c8;
    const float v0 = c16;         // shfl hop weights c16^(2^k)
    const float v1 = v0 * v0;
    const float v2 = v1 * v1;
    const float v3 = v2 * v2;
    const float v4 = v3 * v3;     // c^256
    const float ct = v4 * v4;     // c^512: cross-tile carry weight
    const float inv_c16 = 1.0f / c16;

    // clane = c16^lane (exact square-and-multiply)
    float clane = 1.0f;
    {
        float bp = c16;
        if (lane & 1)  clane *= bp;  bp *= bp;
        if (lane & 2)  clane *= bp;  bp *= bp;
        if (lane & 4)  clane *= bp;  bp *= bp;
        if (lane & 8)  clane *= bp;  bp *= bp;
        if (lane & 16) clane *= bp;
    }

    const int start_out = (ck == CPR - 1) ? (T - CHUNK) : ck * CHUNK;
    const float* __restrict__ xrow = x   + (size_t)row * (size_t)T;
    float* __restrict__       orow = out + (size_t)row * (size_t)T;

    // pass-1 aggregate of one 512-tile: rolling, no arrays
    auto agg16 = [&](const float* xp) -> float {
        const float4 va = *reinterpret_cast<const float4*>(xp);
        const float4 vb = *reinterpret_cast<const float4*>(xp + 4);
        const float4 vc = *reinterpret_cast<const float4*>(xp + 8);
        const float4 vd = *reinterpret_cast<const float4*>(xp + 12);
        float lp;
        lp =             fmaf(s, va.x, se);
        lp = fmaf(c, lp, fmaf(s, va.y, se));
        lp = fmaf(c, lp, fmaf(s, va.z, se));
        lp = fmaf(c, lp, fmaf(s, va.w, se));
        lp = fmaf(c, lp, fmaf(s, vb.x, se));
        lp = fmaf(c, lp, fmaf(s, vb.y, se));
        lp = fmaf(c, lp, fmaf(s, vb.z, se));
        lp = fmaf(c, lp, fmaf(s, vb.w, se));
        lp = fmaf(c, lp, fmaf(s, vc.x, se));
        lp = fmaf(c, lp, fmaf(s, vc.y, se));
        lp = fmaf(c, lp, fmaf(s, vc.z, se));
        lp = fmaf(c, lp, fmaf(s, vc.w, se));
        lp = fmaf(c, lp, fmaf(s, vd.x, se));
        lp = fmaf(c, lp, fmaf(s, vd.y, se));
        lp = fmaf(c, lp, fmaf(s, vd.z, se));
        lp = fmaf(c, lp, fmaf(s, vd.w, se));
        return lp;
    };
    auto warpscan = [&](float P) -> float {
        float u;
        u = __shfl_up_sync(FULL_MASK, P, 1);  if (lane >= 1)  P = fmaf(v0, u, P);
        u = __shfl_up_sync(FULL_MASK, P, 2);  if (lane >= 2)  P = fmaf(v1, u, P);
        u = __shfl_up_sync(FULL_MASK, P, 4);  if (lane >= 4)  P = fmaf(v2, u, P);
        u = __shfl_up_sync(FULL_MASK, P, 8);  if (lane >= 8)  P = fmaf(v3, u, P);
        u = __shfl_up_sync(FULL_MASK, P, 16); if (lane >= 16) P = fmaf(v4, u, P);
        return P;
    };
    // pass-2: exact sequential recurrence over one float4, epilogue + store
    auto emit4 = [&](const float4& v, float& n, float* op) {
        float4 o;
        n = fmaf(c, n, fmaf(s, v.x, se));
        float g = f_ex2(-a * f_lg2(n));
        o.x = fmaf(v.x, g, d);
        n = fmaf(c, n, fmaf(s, v.y, se));
        g = f_ex2(-a * f_lg2(n));
        o.y = fmaf(v.y, g, d);
        n = fmaf(c, n, fmaf(s, v.z, se));
        g = f_ex2(-a * f_lg2(n));
        o.z = fmaf(v.z, g, d);
        n = fmaf(c, n, fmaf(s, v.w, se));
        g = f_ex2(-a * f_lg2(n));
        o.w = fmaf(v.w, g, d);
        if (r2) {
            o.x = f_sqrt(o.x) - dr;
            o.y = f_sqrt(o.y) - dr;
            o.z = f_sqrt(o.z) - dr;
            o.w = f_sqrt(o.w) - dr;
        } else {
            o.x = f_ex2(inv_r * f_lg2(o.x)) - dr;
            o.y = f_ex2(inv_r * f_lg2(o.y)) - dr;
            o.z = f_ex2(inv_r * f_lg2(o.z)) - dr;
            o.w = f_ex2(inv_r * f_lg2(o.w)) - dr;
        }
        st_cs(op, o);
    };

    float n_prev;
    if (ck == 0) {
        n_prev = __ldg(xrow) + 1e-6f;   // virtual carry -> n[0] = x[0]+eps exact
    } else {
        // warm tile: pass-1 only, zero carry-in (drops ~c^512 term)
        const float lp = agg16(xrow + start_out - WARM + lane * 16);
        n_prev = __shfl_sync(FULL_MASK, warpscan(lp), 31);
    }

    #pragma unroll
    for (int it = 0; it < CHUNK / TILE; ++it) {
        const float* xp = xrow + start_out + it * TILE + lane * 16;
        float*       op = orow + start_out + it * TILE + lane * 16;

        // pass 1: aggregate + cross-lane scan
        const float lp = agg16(xp);
        const float P  = warpscan(lp);

        // kexcl = P_{lane-1}, recovered locally: P = lp + c16*kexcl
        const float kexcl = (P - lp) * inv_c16;
        const float kappa = fmaf(clane, n_prev, kexcl);

        const float P31 = __shfl_sync(FULL_MASK, P, 31);
        n_prev = fmaf(ct, n_prev, P31);

        // pass 2: re-load (L1 hits) and run exact recurrence from kappa
        float n = kappa;
        emit4(*reinterpret_cast<const float4*>(xp),      n, op);
        emit4(*reinterpret_cast<const float4*>(xp + 4),  n, op + 4);
        emit4(*reinterpret_cast<const float4*>(xp + 8),  n, op + 8);
        emit4(*reinterpret_cast<const float4*>(xp + 12), n, op + 12);
    }
}

extern "C" void kernel_launch(void* const* d_in, const int* in_sizes, int n_in,
                              void* d_out, int out_size)
{
    const float* x      = (const float*)d_in[0];
    const float* smooth = (const float*)d_in[1];
    const float* alpha  = (const float*)d_in[2];
    const float* delta  = (const float*)d_in[3];
    const float* root   = (const float*)d_in[4];
    float* out = (float*)d_out;

    const int T = 6000;
    const int rows = in_sizes[0] / T;   // 2560

    const long long warps = (long long)rows * CPR;   // 15360
    const int grid = (int)((warps + 3) / 4);         // 4 warps/block
    pcen_kernel<<<grid, 128>>>(x, smooth, alpha, delta, root, out, rows, T);
}